// round 8
// baseline (speedup 1.0000x reference)
#include <cuda_runtime.h>
#include <cuda_fp16.h>
#include <math.h>
#include <stdint.h>

// Problem constants
#define B_   2
#define S_   2048
#define DM_  1024
#define H_   16
#define KVH_ 4
#define NG_  4          // H_/KVH_
#define DH_  64
#define WINDOW_ 256
#define NGLOBAL_ 4
#define ATTN_SCALE_ 0.125f   // 1/sqrt(64)
#define M_TOT (B_ * S_)      // 4096

// Scratch (static device allocations; no cudaMalloc allowed)
__device__ __half g_x16 [(size_t)M_TOT * DM_];            // x, fp16
__device__ __half g_wq16[(size_t)DM_ * DM_];              // Wq [k][n] fp16
__device__ __half g_wk16[(size_t)DM_ * (KVH_ * DH_)];     // Wk [k][n]
__device__ __half g_wv16[(size_t)DM_ * (KVH_ * DH_)];     // Wv [k][n]
__device__ __half g_wo16[(size_t)DM_ * DM_];              // Wo [k][n]
__device__ __half g_q16 [(size_t)B_ * H_ * S_ * DH_];     // [b,h,s,d]
__device__ __half g_k16 [(size_t)B_ * KVH_ * S_ * DH_];   // [b,kvh,s,d]
__device__ __half g_v16 [(size_t)B_ * KVH_ * S_ * DH_];   // [b,kvh,s,d]
__device__ __half g_ctx16[(size_t)M_TOT * DM_];           // [b,s,h,d] fp16

#define MMA_F16(D, A, B)                                                      \
    asm volatile(                                                             \
        "mma.sync.aligned.m16n8k16.row.col.f32.f16.f16.f32 "                  \
        "{%0,%1,%2,%3}, {%4,%5,%6,%7}, {%8,%9}, {%0,%1,%2,%3};\n"             \
        : "+f"((D)[0]), "+f"((D)[1]), "+f"((D)[2]), "+f"((D)[3])              \
        : "r"((A)[0]), "r"((A)[1]), "r"((A)[2]), "r"((A)[3]),                 \
          "r"((B)[0]), "r"((B)[1]))

#define LDMX4(R, addr)                                                        \
    asm volatile("ldmatrix.sync.aligned.m8n8.x4.shared.b16 {%0,%1,%2,%3}, [%4];" \
        : "=r"((R)[0]), "=r"((R)[1]), "=r"((R)[2]), "=r"((R)[3]) : "r"(addr))

#define LDMX4T(R, addr)                                                       \
    asm volatile("ldmatrix.sync.aligned.m8n8.x4.trans.shared.b16 {%0,%1,%2,%3}, [%4];" \
        : "=r"((R)[0]), "=r"((R)[1]), "=r"((R)[2]), "=r"((R)[3]) : "r"(addr))

__device__ __forceinline__ uint32_t smem_u32(const void* p) {
    uint32_t a;
    asm("{ .reg .u64 t; cvta.to.shared.u64 t, %1; cvt.u32.u64 %0, t; }" : "=r"(a) : "l"(p));
    return a;
}

__device__ __forceinline__ uint32_t pack_h2(float a, float b) {
    __half2 t = __floats2half2_rn(a, b);
    return *reinterpret_cast<uint32_t*>(&t);
}

// ---------------------------------------------------------------------------
// fp32 -> fp16 conversion kernels
// ---------------------------------------------------------------------------
__global__ void cvt_half_kernel(const float* __restrict__ in, __half* __restrict__ out, int n4)
{
    int i = blockIdx.x * blockDim.x + threadIdx.x;
    int stride = gridDim.x * blockDim.x;
    for (; i < n4; i += stride) {
        float4 v = ((const float4*)in)[i];
        ((__half2*)out)[2 * i]     = __floats2half2_rn(v.x, v.y);
        ((__half2*)out)[2 * i + 1] = __floats2half2_rn(v.z, v.w);
    }
}

__global__ void cvt_weights_kernel(const float* __restrict__ wq, const float* __restrict__ wk,
                                   const float* __restrict__ wv, const float* __restrict__ wo,
                                   __half* __restrict__ oq, __half* __restrict__ ok,
                                   __half* __restrict__ ov, __half* __restrict__ oo)
{
    int i = blockIdx.x * blockDim.x + threadIdx.x;
    int stride = gridDim.x * blockDim.x;
    for (; i < 655360; i += stride) {
        const float* src; __half* dst; int j;
        if (i < 262144)      { src = wq; dst = oq; j = i; }
        else if (i < 327680) { src = wk; dst = ok; j = i - 262144; }
        else if (i < 393216) { src = wv; dst = ov; j = i - 327680; }
        else                 { src = wo; dst = oo; j = i - 393216; }
        float4 v = ((const float4*)src)[j];
        ((__half2*)dst)[2 * j]     = __floats2half2_rn(v.x, v.y);
        ((__half2*)dst)[2 * j + 1] = __floats2half2_rn(v.z, v.w);
    }
}

// ---------------------------------------------------------------------------
// fp16 tensor-core GEMM (unchanged from R7): C = A[M,1024] @ W[1024,N].
// ---------------------------------------------------------------------------
#define APITCH 40
#define BPITCH 136

__global__ __launch_bounds__(256) void h16_gemm(const __half* __restrict__ A,
                                                const __half* __restrict__ WQ,
                                                const __half* __restrict__ WK,
                                                const __half* __restrict__ WV,
                                                void* oQ, void* oK, void* oV, int mode)
{
    __shared__ __align__(16) __half As[2][128 * APITCH];
    __shared__ __align__(16) __half Bs[2][32 * BPITCH];

    const int tid  = threadIdx.x;
    const int wid  = tid >> 5;
    const int lane = tid & 31;
    const int g    = lane >> 2;
    const int q    = lane & 3;
    const int bx   = blockIdx.x;
    const int m0   = blockIdx.y * 128;
    const int wm   = (wid >> 2) * 64;
    const int wn   = (wid & 3) * 32;

    const __half* W; void* outp; int N, n0, nh;
    if (mode == 1)    { W = WQ; outp = oQ; N = 1024; n0 = bx * 128;        nh = H_; }
    else if (bx < 8)  { W = WQ; outp = oQ; N = 1024; n0 = bx * 128;        nh = H_; }
    else if (bx < 10) { W = WK; outp = oK; N = 256;  n0 = (bx - 8) * 128;  nh = KVH_; }
    else              { W = WV; outp = oV; N = 256;  n0 = (bx - 10) * 128; nh = KVH_; }

    float acc[4][4][4];
#pragma unroll
    for (int i = 0; i < 4; ++i)
#pragma unroll
        for (int j = 0; j < 4; ++j)
#pragma unroll
            for (int r = 0; r < 4; ++r) acc[i][j][r] = 0.f;

    const __half* aSrc = A + (size_t)(m0 + (tid >> 1)) * DM_ + (tid & 1) * 16;
    const __half* bSrc = W + (size_t)(tid >> 3) * N + n0 + (tid & 7) * 16;
    const int aOff = (tid >> 1) * APITCH + (tid & 1) * 16;
    const int bOff = (tid >> 3) * BPITCH + (tid & 7) * 16;

    const uint32_t sA0 = smem_u32(As[0]);
    const uint32_t sA1 = smem_u32(As[1]);
    const uint32_t sB0 = smem_u32(Bs[0]);
    const uint32_t sB1 = smem_u32(Bs[1]);

    const int aFragRow = wm + (lane & 7) + 8 * ((lane >> 3) & 1);
    const int aFragCol = 8 * (lane >> 4);
    const int bFragRow = (lane & 7) + 8 * ((lane >> 3) & 1);
    const int bFragCol = wn + 8 * (lane >> 4);

    uint4 ra[2], rb[2];
#pragma unroll
    for (int i = 0; i < 2; ++i) {
        ra[i] = *(const uint4*)(aSrc + i * 8);
        rb[i] = *(const uint4*)(bSrc + i * 8);
    }
#pragma unroll
    for (int i = 0; i < 2; ++i) {
        *(uint4*)(&As[0][aOff + i * 8]) = ra[i];
        *(uint4*)(&Bs[0][bOff + i * 8]) = rb[i];
    }
    __syncthreads();

    int buf = 0;
    const int T = DM_ / 32;
    for (int t = 0; t < T; ++t) {
        if (t + 1 < T) {
            const __half* a2 = aSrc + (t + 1) * 32;
            const __half* b2 = bSrc + (size_t)(t + 1) * 32 * N;
#pragma unroll
            for (int i = 0; i < 2; ++i) {
                ra[i] = *(const uint4*)(a2 + i * 8);
                rb[i] = *(const uint4*)(b2 + i * 8);
            }
        }

        const uint32_t sA = buf ? sA1 : sA0;
        const uint32_t sB = buf ? sB1 : sB0;
#pragma unroll
        for (int kk = 0; kk < 2; ++kk) {
            uint32_t af[4][4], bf[2][4];
#pragma unroll
            for (int mf = 0; mf < 4; ++mf) {
                uint32_t addr = sA + (uint32_t)((aFragRow + mf * 16) * APITCH +
                                                kk * 16 + aFragCol) * 2;
                LDMX4(af[mf], addr);
            }
#pragma unroll
            for (int np = 0; np < 2; ++np) {
                uint32_t addr = sB + (uint32_t)((kk * 16 + bFragRow) * BPITCH +
                                                bFragCol + np * 16) * 2;
                LDMX4T(bf[np], addr);
            }
#pragma unroll
            for (int mf = 0; mf < 4; ++mf)
#pragma unroll
                for (int np = 0; np < 2; ++np) {
                    MMA_F16(acc[mf][np * 2],     af[mf], (&bf[np][0]));
                    MMA_F16(acc[mf][np * 2 + 1], af[mf], (&bf[np][2]));
                }
        }

        if (t + 1 < T) {
            const int nb = buf ^ 1;
#pragma unroll
            for (int i = 0; i < 2; ++i) {
                *(uint4*)(&As[nb][aOff + i * 8]) = ra[i];
                *(uint4*)(&Bs[nb][bOff + i * 8]) = rb[i];
            }
        }
        __syncthreads();
        buf ^= 1;
    }

#pragma unroll
    for (int mf = 0; mf < 4; ++mf) {
        const int row0 = m0 + wm + mf * 16 + g;
        const int row1 = row0 + 8;
#pragma unroll
        for (int nf = 0; nf < 4; ++nf) {
            const int col0 = n0 + wn + nf * 8 + q * 2;
            if (mode == 1) {
                float* C = (float*)outp;
                *(float2*)(&C[(size_t)row0 * 1024 + col0]) =
                    make_float2(acc[mf][nf][0], acc[mf][nf][1]);
                *(float2*)(&C[(size_t)row1 * 1024 + col0]) =
                    make_float2(acc[mf][nf][2], acc[mf][nf][3]);
            } else {
                __half* C = (__half*)outp;
                const int h = col0 >> 6, d = col0 & 63;
                {
                    int b = row0 >> 11, s = row0 & (S_ - 1);
                    *(__half2*)(&C[((((size_t)b * nh + h) * S_) + s) * DH_ + d]) =
                        __floats2half2_rn(acc[mf][nf][0], acc[mf][nf][1]);
                }
                {
                    int b = row1 >> 11, s = row1 & (S_ - 1);
                    *(__half2*)(&C[((((size_t)b * nh + h) * S_) + s) * DH_ + d]) =
                        __floats2half2_rn(acc[mf][nf][2], acc[mf][nf][3]);
                }
            }
        }
    }
}

// ---------------------------------------------------------------------------
// L2-normalize + RoPE, fp16 in-place. Thread-per-row, uint4 I/O.
// ---------------------------------------------------------------------------
#define NQROWS (B_ * H_ * S_)     // 65536
#define NKROWS (B_ * KVH_ * S_)   // 16384

__global__ __launch_bounds__(256) void norm_rope16_kernel(__half* __restrict__ qh,
                                                          __half* __restrict__ kh,
                                                          const float* __restrict__ cosb,
                                                          const float* __restrict__ sinb)
{
    int idx = blockIdx.x * 256 + threadIdx.x;
    if (idx >= NQROWS + NKROWS) return;
    __half* row = (idx < NQROWS) ? (qh + (size_t)idx * DH_)
                                 : (kh + (size_t)(idx - NQROWS) * DH_);
    int s = idx & (S_ - 1);

    uint4 rv[8];
#pragma unroll
    for (int j = 0; j < 8; ++j) rv[j] = *(const uint4*)(row + j * 8);

    float ss = 0.f;
#pragma unroll
    for (int j = 0; j < 8; ++j) {
        const __half2* hp = (const __half2*)&rv[j];
#pragma unroll
        for (int t = 0; t < 4; ++t) {
            float2 f = __half22float2(hp[t]);
            ss += f.x * f.x + f.y * f.y;
        }
    }
    const float inv = 1.0f / (sqrtf(ss) + 1e-8f);

    const float4* cb = (const float4*)(cosb + s * 32);
    const float4* sb = (const float4*)(sinb + s * 32);
#pragma unroll
    for (int j = 0; j < 4; ++j) {
        const __half2* x1 = (const __half2*)&rv[j];
        const __half2* x2 = (const __half2*)&rv[j + 4];
        float4 c0 = cb[2 * j], c1 = cb[2 * j + 1];
        float4 s0 = sb[2 * j], s1 = sb[2 * j + 1];
        float cc[8] = {c0.x, c0.y, c0.z, c0.w, c1.x, c1.y, c1.z, c1.w};
        float sn[8] = {s0.x, s0.y, s0.z, s0.w, s1.x, s1.y, s1.z, s1.w};
        uint4 o1, o2;
        __half2* o1p = (__half2*)&o1;
        __half2* o2p = (__half2*)&o2;
#pragma unroll
        for (int t = 0; t < 4; ++t) {
            float2 a  = __half22float2(x1[t]);
            float2 bq = __half22float2(x2[t]);
            a.x *= inv; a.y *= inv; bq.x *= inv; bq.y *= inv;
            o1p[t] = __floats2half2_rn(a.x * cc[2 * t]     - bq.x * sn[2 * t],
                                       a.y * cc[2 * t + 1] - bq.y * sn[2 * t + 1]);
            o2p[t] = __floats2half2_rn(a.x * sn[2 * t]     + bq.x * cc[2 * t],
                                       a.y * sn[2 * t + 1] + bq.y * cc[2 * t + 1]);
        }
        *(uint4*)(row + j * 8)      = o1;
        *(uint4*)(row + 32 + j * 8) = o2;
    }
}

// ---------------------------------------------------------------------------
// Flash attention, fp16 mma, GQA-shared K/V.
// Block = 64 queries x 4 heads of one kv group; 256 threads = 8 warps.
// Warp w: head (w>>1), query half (w&1)*32; warp tile m32 x n64 (2 m16 tiles).
// K/V double-buffered via cp.async; P stays in registers (accum layout == A
// operand layout for m16n8k16).
// ---------------------------------------------------------------------------
#define KP 72

__global__ __launch_bounds__(256) void attn_h16_kernel(const __half* __restrict__ Q,
                                                       const __half* __restrict__ Kb,
                                                       const __half* __restrict__ Vb,
                                                       __half* __restrict__ ctx)
{
    __shared__ __align__(16) __half Ks[2][64 * KP];
    __shared__ __align__(16) __half Vs[2][64 * KP];

    const int tid  = threadIdx.x;
    const int lane = tid & 31;
    const int w    = tid >> 5;
    const int g    = lane >> 2;
    const int qq   = lane & 3;
    const int b    = blockIdx.z;
    const int kvh  = blockIdx.y;
    const int q0   = blockIdx.x * 64;
    const int hh   = w >> 1;
    const int h    = kvh * NG_ + hh;
    const int mhalf = (w & 1) * 32;

    const __half* Kbase = Kb + (((size_t)b * KVH_ + kvh) * S_) * DH_;
    const __half* Vbase = Vb + (((size_t)b * KVH_ + kvh) * S_) * DH_;

    const uint32_t sK0 = smem_u32(Ks[0]);
    const uint32_t sK1 = smem_u32(Ks[1]);
    const uint32_t sV0 = smem_u32(Vs[0]);
    const uint32_t sV1 = smem_u32(Vs[1]);

    const int aRow  = (lane & 7) + 8 * ((lane >> 3) & 1);
    const int aCol  = 8 * (lane >> 4);
    const int bRowK = (lane & 7) + 8 * (lane >> 4);
    const int bColK = 8 * ((lane >> 3) & 1);
    const int bRowV = (lane & 7) + 8 * ((lane >> 3) & 1);
    const int bColV = 8 * (lane >> 4);

    int q_lo = q0 - (WINDOW_ - 1); if (q_lo < 0) q_lo = 0;
    const int c_lo = q_lo >> 6;
    const int c_hi = q0 >> 6;
    const int nch  = c_hi - c_lo + 1 + (c_lo > 0 ? 1 : 0);

    auto chunk_of = [&](int i) -> int {
        return (c_lo > 0) ? (i == 0 ? 0 : c_lo + i - 1) : (c_lo + i);
    };
    auto issue_kv = [&](int i, int buf) {
        const int c = chunk_of(i);
        const uint32_t sk = buf ? sK1 : sK0;
        const uint32_t sv = buf ? sV1 : sV0;
#pragma unroll
        for (int p = 0; p < 2; ++p) {
            int id = p * 256 + tid;
            int r = id >> 3, cc = (id & 7) * 8;
            const __half* kg = &Kbase[((size_t)(c * 64 + r)) * DH_ + cc];
            const __half* vg = &Vbase[((size_t)(c * 64 + r)) * DH_ + cc];
            uint32_t kd = sk + (uint32_t)(r * KP + cc) * 2;
            uint32_t vd = sv + (uint32_t)(r * KP + cc) * 2;
            asm volatile("cp.async.cg.shared.global [%0], [%1], 16;" :: "r"(kd), "l"(kg));
            asm volatile("cp.async.cg.shared.global [%0], [%1], 16;" :: "r"(vd), "l"(vg));
        }
        asm volatile("cp.async.commit_group;" ::: "memory");
    };

    // ---- prologue: launch chunk 0 load; stage Q (4 heads) through Ks[1] ----
    issue_kv(0, 0);

    uint32_t qf[2][4][4];
    for (int t = 0; t < 4; ++t) {
        const __half* Qb = Q + ((((size_t)b * H_ + (kvh * NG_ + t)) * S_) + q0) * DH_;
        __syncthreads();
#pragma unroll
        for (int p = 0; p < 2; ++p) {
            int id = p * 256 + tid;
            int r = id >> 3, cc = (id & 7) * 8;
            *(uint4*)(&Ks[1][r * KP + cc]) = *(const uint4*)(&Qb[(size_t)r * DH_ + cc]);
        }
        __syncthreads();
        if (hh == t) {
#pragma unroll
            for (int mt = 0; mt < 2; ++mt)
#pragma unroll
                for (int kk = 0; kk < 4; ++kk) {
                    uint32_t addr = sK1 + (uint32_t)((mhalf + mt * 16 + aRow) * KP +
                                                     kk * 16 + aCol) * 2;
                    LDMX4(qf[mt][kk], addr);
                }
        }
    }
    __syncthreads();
    if (nch > 1) issue_kv(1, 1);

    float o[2][8][4];
#pragma unroll
    for (int mt = 0; mt < 2; ++mt)
#pragma unroll
        for (int nf = 0; nf < 8; ++nf)
#pragma unroll
            for (int j = 0; j < 4; ++j) o[mt][nf][j] = 0.f;
    float mM[2][2] = {{-INFINITY, -INFINITY}, {-INFINITY, -INFINITY}};
    float lL[2][2] = {{0.f, 0.f}, {0.f, 0.f}};

    for (int it = 0; it < nch; ++it) {
        if (it + 1 >= nch) asm volatile("cp.async.wait_group 0;" ::: "memory");
        else               asm volatile("cp.async.wait_group 1;" ::: "memory");
        __syncthreads();

        const int buf = it & 1;
        const uint32_t sK = buf ? sK1 : sK0;
        const uint32_t sV = buf ? sV1 : sV0;
        const int c = chunk_of(it);

        // ---- S = Q K^T ----
        float s[2][8][4];
#pragma unroll
        for (int mt = 0; mt < 2; ++mt)
#pragma unroll
            for (int nf = 0; nf < 8; ++nf)
#pragma unroll
                for (int j = 0; j < 4; ++j) s[mt][nf][j] = 0.f;

#pragma unroll
        for (int kk = 0; kk < 4; ++kk)
#pragma unroll
            for (int np = 0; np < 4; ++np) {
                uint32_t bf[4];
                uint32_t addr = sK + (uint32_t)((np * 16 + bRowK) * KP +
                                                kk * 16 + bColK) * 2;
                LDMX4(bf, addr);
                MMA_F16(s[0][np * 2],     qf[0][kk], (&bf[0]));
                MMA_F16(s[0][np * 2 + 1], qf[0][kk], (&bf[2]));
                MMA_F16(s[1][np * 2],     qf[1][kk], (&bf[0]));
                MMA_F16(s[1][np * 2 + 1], qf[1][kk], (&bf[2]));
            }

        // ---- softcap + mask + online softmax (per m-tile) ----
#pragma unroll
        for (int mt = 0; mt < 2; ++mt) {
            const int r0 = q0 + mhalf + mt * 16 + g;
            const int r1 = r0 + 8;
            float rmax0 = -INFINITY, rmax1 = -INFINITY;
#pragma unroll
            for (int nf = 0; nf < 8; ++nf) {
                const int kc0 = c * 64 + nf * 8 + 2 * qq;
#pragma unroll
                for (int j = 0; j < 4; ++j) {
                    const int kc = kc0 + (j & 1);
                    const int qr = (j < 2) ? r0 : r1;
                    float x = s[mt][nf][j] * ATTN_SCALE_;
                    float e = __expf(x * (2.0f / 15.0f));
                    x = 15.0f * ((e - 1.0f) / (e + 1.0f));
                    bool valid = (kc <= qr) && ((kc + WINDOW_ > qr) || (kc < NGLOBAL_));
                    x = valid ? x : -INFINITY;
                    s[mt][nf][j] = x;
                    if (j < 2) rmax0 = fmaxf(rmax0, x); else rmax1 = fmaxf(rmax1, x);
                }
            }
            rmax0 = fmaxf(rmax0, __shfl_xor_sync(0xffffffffu, rmax0, 1));
            rmax0 = fmaxf(rmax0, __shfl_xor_sync(0xffffffffu, rmax0, 2));
            rmax1 = fmaxf(rmax1, __shfl_xor_sync(0xffffffffu, rmax1, 1));
            rmax1 = fmaxf(rmax1, __shfl_xor_sync(0xffffffffu, rmax1, 2));

            const float mn0 = fmaxf(fmaxf(mM[mt][0], rmax0), -1e30f);
            const float mn1 = fmaxf(fmaxf(mM[mt][1], rmax1), -1e30f);
            const float a0 = __expf(mM[mt][0] - mn0);
            const float a1 = __expf(mM[mt][1] - mn1);

            float rs0 = 0.f, rs1 = 0.f;
#pragma unroll
            for (int nf = 0; nf < 8; ++nf) {
                float p0 = __expf(s[mt][nf][0] - mn0);
                float p1 = __expf(s[mt][nf][1] - mn0);
                float p2 = __expf(s[mt][nf][2] - mn1);
                float p3 = __expf(s[mt][nf][3] - mn1);
                rs0 += p0 + p1; rs1 += p2 + p3;
                s[mt][nf][0] = p0; s[mt][nf][1] = p1;
                s[mt][nf][2] = p2; s[mt][nf][3] = p3;
            }
            rs0 += __shfl_xor_sync(0xffffffffu, rs0, 1);
            rs0 += __shfl_xor_sync(0xffffffffu, rs0, 2);
            rs1 += __shfl_xor_sync(0xffffffffu, rs1, 1);
            rs1 += __shfl_xor_sync(0xffffffffu, rs1, 2);
            lL[mt][0] = lL[mt][0] * a0 + rs0;
            lL[mt][1] = lL[mt][1] * a1 + rs1;
#pragma unroll
            for (int nf = 0; nf < 8; ++nf) {
                o[mt][nf][0] *= a0; o[mt][nf][1] *= a0;
                o[mt][nf][2] *= a1; o[mt][nf][3] *= a1;
            }
            mM[mt][0] = mn0; mM[mt][1] = mn1;
        }

        // ---- O += P V (P packed from accumulator registers) ----
#pragma unroll
        for (int kk = 0; kk < 4; ++kk) {
            uint32_t af0[4], af1[4];
            af0[0] = pack_h2(s[0][2 * kk][0],     s[0][2 * kk][1]);
            af0[1] = pack_h2(s[0][2 * kk][2],     s[0][2 * kk][3]);
            af0[2] = pack_h2(s[0][2 * kk + 1][0], s[0][2 * kk + 1][1]);
            af0[3] = pack_h2(s[0][2 * kk + 1][2], s[0][2 * kk + 1][3]);
            af1[0] = pack_h2(s[1][2 * kk][0],     s[1][2 * kk][1]);
            af1[1] = pack_h2(s[1][2 * kk][2],     s[1][2 * kk][3]);
            af1[2] = pack_h2(s[1][2 * kk + 1][0], s[1][2 * kk + 1][1]);
            af1[3] = pack_h2(s[1][2 * kk + 1][2], s[1][2 * kk + 1][3]);
#pragma unroll
            for (int np = 0; np < 4; ++np) {
                uint32_t bv[4];
                uint32_t addr = sV + (uint32_t)((kk * 16 + bRowV) * KP +
                                                np * 16 + bColV) * 2;
                LDMX4T(bv, addr);
                MMA_F16(o[0][np * 2],     af0, (&bv[0]));
                MMA_F16(o[0][np * 2 + 1], af0, (&bv[2]));
                MMA_F16(o[1][np * 2],     af1, (&bv[0]));
                MMA_F16(o[1][np * 2 + 1], af1, (&bv[2]));
            }
        }

        __syncthreads();   // everyone done with buf before refill
        if (it + 2 < nch) issue_kv(it + 2, buf);
    }

    // ---- epilogue: normalize, write fp16 ctx[b][s][h][d] ----
#pragma unroll
    for (int mt = 0; mt < 2; ++mt) {
        const int r0 = q0 + mhalf + mt * 16 + g;
        const int r1 = r0 + 8;
        const float inv0 = 1.0f / lL[mt][0];
        const float inv1 = 1.0f / lL[mt][1];
        __half* c0p = ctx + ((((size_t)b * S_ + r0) * H_) + h) * DH_;
        __half* c1p = ctx + ((((size_t)b * S_ + r1) * H_) + h) * DH_;
#pragma unroll
        for (int nf = 0; nf < 8; ++nf) {
            const int d = nf * 8 + 2 * qq;
            *(__half2*)(&c0p[d]) = __floats2half2_rn(o[mt][nf][0] * inv0,
                                                     o[mt][nf][1] * inv0);
            *(__half2*)(&c1p[d]) = __floats2half2_rn(o[mt][nf][2] * inv1,
                                                     o[mt][nf][3] * inv1);
        }
    }
}

// ---------------------------------------------------------------------------
// Launch
// ---------------------------------------------------------------------------
extern "C" void kernel_launch(void* const* d_in, const int* in_sizes, int n_in,
                              void* d_out, int out_size)
{
    const float* x    = (const float*)d_in[0];
    const float* cosb = (const float*)d_in[1];
    const float* sinb = (const float*)d_in[2];
    // d_in[3] = mask (pure causal) — computed analytically, unused
    const float* Wq   = (const float*)d_in[4];
    const float* Wk   = (const float*)d_in[5];
    const float* Wv   = (const float*)d_in[6];
    const float* Wo   = (const float*)d_in[7];
    float* out        = (float*)d_out;

    __half *x16, *wq16, *wk16, *wv16, *wo16, *q16, *k16, *v16, *ctx16;
    cudaGetSymbolAddress((void**)&x16,   g_x16);
    cudaGetSymbolAddress((void**)&wq16,  g_wq16);
    cudaGetSymbolAddress((void**)&wk16,  g_wk16);
    cudaGetSymbolAddress((void**)&wv16,  g_wv16);
    cudaGetSymbolAddress((void**)&wo16,  g_wo16);
    cudaGetSymbolAddress((void**)&q16,   g_q16);
    cudaGetSymbolAddress((void**)&k16,   g_k16);
    cudaGetSymbolAddress((void**)&v16,   g_v16);
    cudaGetSymbolAddress((void**)&ctx16, g_ctx16);

    // fp16 conversions
    cvt_half_kernel<<<2048, 256>>>(x, x16, (M_TOT * DM_) / 4);
    cvt_weights_kernel<<<1280, 256>>>(Wq, Wk, Wv, Wo, wq16, wk16, wv16, wo16);

    // Fused QKV projections (fp16 tensor cores), scatter to [b,h,s,d] fp16
    h16_gemm<<<dim3(12, M_TOT / 128), 256>>>(x16, wq16, wk16, wv16, q16, k16, v16, 0);

    // L2-norm + RoPE (q and k, fp16 in-place, single launch, thread-per-row)
    norm_rope16_kernel<<<(NQROWS + NKROWS + 255) / 256, 256>>>(q16, k16, cosb, sinb);

    // Flash attention (fp16 mma, GQA-shared K/V)
    attn_h16_kernel<<<dim3(S_ / 64, KVH_, B_), dim3(256)>>>(q16, k16, v16, ctx16);

    // Output projection (fp16 mma, fp32 row-major into d_out)
    h16_gemm<<<dim3(8, M_TOT / 128), 256>>>(ctx16, wo16, nullptr, nullptr,
                                            out, nullptr, nullptr, 1);
}

// round 9
// speedup vs baseline: 1.3494x; 1.3494x over previous
#include <cuda_runtime.h>
#include <cuda_fp16.h>
#include <math.h>
#include <stdint.h>

// Problem constants
#define B_   2
#define S_   2048
#define DM_  1024
#define H_   16
#define KVH_ 4
#define NG_  4          // H_/KVH_
#define DH_  64
#define WINDOW_ 256
#define NGLOBAL_ 4
#define ATTN_SCALE_ 0.125f   // 1/sqrt(64)
#define M_TOT (B_ * S_)      // 4096

// Scratch (static device allocations; no cudaMalloc allowed)
__device__ __half g_x16 [(size_t)M_TOT * DM_];            // x, fp16
__device__ __half g_wq16[(size_t)DM_ * DM_];              // Wq [k][n] fp16
__device__ __half g_wk16[(size_t)DM_ * (KVH_ * DH_)];     // Wk [k][n]
__device__ __half g_wv16[(size_t)DM_ * (KVH_ * DH_)];     // Wv [k][n]
__device__ __half g_wo16[(size_t)DM_ * DM_];              // Wo [k][n]
__device__ __half g_q16 [(size_t)B_ * H_ * S_ * DH_];     // [b,h,s,d]
__device__ __half g_k16 [(size_t)B_ * KVH_ * S_ * DH_];   // [b,kvh,s,d]
__device__ __half g_v16 [(size_t)B_ * KVH_ * S_ * DH_];   // [b,kvh,s,d]
__device__ __half g_ctx16[(size_t)M_TOT * DM_];           // [b,s,h,d] fp16

#define MMA_F16(D, A, B)                                                      \
    asm volatile(                                                             \
        "mma.sync.aligned.m16n8k16.row.col.f32.f16.f16.f32 "                  \
        "{%0,%1,%2,%3}, {%4,%5,%6,%7}, {%8,%9}, {%0,%1,%2,%3};\n"             \
        : "+f"((D)[0]), "+f"((D)[1]), "+f"((D)[2]), "+f"((D)[3])              \
        : "r"((A)[0]), "r"((A)[1]), "r"((A)[2]), "r"((A)[3]),                 \
          "r"((B)[0]), "r"((B)[1]))

#define LDMX4(R, addr)                                                        \
    asm volatile("ldmatrix.sync.aligned.m8n8.x4.shared.b16 {%0,%1,%2,%3}, [%4];" \
        : "=r"((R)[0]), "=r"((R)[1]), "=r"((R)[2]), "=r"((R)[3]) : "r"(addr))

#define LDMX4T(R, addr)                                                       \
    asm volatile("ldmatrix.sync.aligned.m8n8.x4.trans.shared.b16 {%0,%1,%2,%3}, [%4];" \
        : "=r"((R)[0]), "=r"((R)[1]), "=r"((R)[2]), "=r"((R)[3]) : "r"(addr))

__device__ __forceinline__ uint32_t smem_u32(const void* p) {
    uint32_t a;
    asm("{ .reg .u64 t; cvta.to.shared.u64 t, %1; cvt.u32.u64 %0, t; }" : "=r"(a) : "l"(p));
    return a;
}

__device__ __forceinline__ uint32_t pack_h2(float a, float b) {
    __half2 t = __floats2half2_rn(a, b);
    return *reinterpret_cast<uint32_t*>(&t);
}

// ---------------------------------------------------------------------------
// fp32 -> fp16 conversion kernels
// ---------------------------------------------------------------------------
__global__ void cvt_half_kernel(const float* __restrict__ in, __half* __restrict__ out, int n4)
{
    int i = blockIdx.x * blockDim.x + threadIdx.x;
    int stride = gridDim.x * blockDim.x;
    for (; i < n4; i += stride) {
        float4 v = ((const float4*)in)[i];
        ((__half2*)out)[2 * i]     = __floats2half2_rn(v.x, v.y);
        ((__half2*)out)[2 * i + 1] = __floats2half2_rn(v.z, v.w);
    }
}

__global__ void cvt_weights_kernel(const float* __restrict__ wq, const float* __restrict__ wk,
                                   const float* __restrict__ wv, const float* __restrict__ wo,
                                   __half* __restrict__ oq, __half* __restrict__ ok,
                                   __half* __restrict__ ov, __half* __restrict__ oo)
{
    int i = blockIdx.x * blockDim.x + threadIdx.x;
    int stride = gridDim.x * blockDim.x;
    for (; i < 655360; i += stride) {
        const float* src; __half* dst; int j;
        if (i < 262144)      { src = wq; dst = oq; j = i; }
        else if (i < 327680) { src = wk; dst = ok; j = i - 262144; }
        else if (i < 393216) { src = wv; dst = ov; j = i - 327680; }
        else                 { src = wo; dst = oo; j = i - 393216; }
        float4 v = ((const float4*)src)[j];
        ((__half2*)dst)[2 * j]     = __floats2half2_rn(v.x, v.y);
        ((__half2*)dst)[2 * j + 1] = __floats2half2_rn(v.z, v.w);
    }
}

// ---------------------------------------------------------------------------
// fp16 tensor-core GEMM (R7, unchanged): C = A[M,1024] @ W[1024,N].
// BM=128, BN=128, BK=32. 256 threads = 8 warps (2m x 4n), warp tile 64x32.
// ---------------------------------------------------------------------------
#define APITCH 40
#define BPITCH 136

__global__ __launch_bounds__(256) void h16_gemm(const __half* __restrict__ A,
                                                const __half* __restrict__ WQ,
                                                const __half* __restrict__ WK,
                                                const __half* __restrict__ WV,
                                                void* oQ, void* oK, void* oV, int mode)
{
    __shared__ __align__(16) __half As[2][128 * APITCH];
    __shared__ __align__(16) __half Bs[2][32 * BPITCH];

    const int tid  = threadIdx.x;
    const int wid  = tid >> 5;
    const int lane = tid & 31;
    const int g    = lane >> 2;
    const int q    = lane & 3;
    const int bx   = blockIdx.x;
    const int m0   = blockIdx.y * 128;
    const int wm   = (wid >> 2) * 64;
    const int wn   = (wid & 3) * 32;

    const __half* W; void* outp; int N, n0, nh;
    if (mode == 1)    { W = WQ; outp = oQ; N = 1024; n0 = bx * 128;        nh = H_; }
    else if (bx < 8)  { W = WQ; outp = oQ; N = 1024; n0 = bx * 128;        nh = H_; }
    else if (bx < 10) { W = WK; outp = oK; N = 256;  n0 = (bx - 8) * 128;  nh = KVH_; }
    else              { W = WV; outp = oV; N = 256;  n0 = (bx - 10) * 128; nh = KVH_; }

    float acc[4][4][4];
#pragma unroll
    for (int i = 0; i < 4; ++i)
#pragma unroll
        for (int j = 0; j < 4; ++j)
#pragma unroll
            for (int r = 0; r < 4; ++r) acc[i][j][r] = 0.f;

    const __half* aSrc = A + (size_t)(m0 + (tid >> 1)) * DM_ + (tid & 1) * 16;
    const __half* bSrc = W + (size_t)(tid >> 3) * N + n0 + (tid & 7) * 16;
    const int aOff = (tid >> 1) * APITCH + (tid & 1) * 16;
    const int bOff = (tid >> 3) * BPITCH + (tid & 7) * 16;

    const uint32_t sA0 = smem_u32(As[0]);
    const uint32_t sA1 = smem_u32(As[1]);
    const uint32_t sB0 = smem_u32(Bs[0]);
    const uint32_t sB1 = smem_u32(Bs[1]);

    const int aFragRow = wm + (lane & 7) + 8 * ((lane >> 3) & 1);
    const int aFragCol = 8 * (lane >> 4);
    const int bFragRow = (lane & 7) + 8 * ((lane >> 3) & 1);
    const int bFragCol = wn + 8 * (lane >> 4);

    uint4 ra[2], rb[2];
#pragma unroll
    for (int i = 0; i < 2; ++i) {
        ra[i] = *(const uint4*)(aSrc + i * 8);
        rb[i] = *(const uint4*)(bSrc + i * 8);
    }
#pragma unroll
    for (int i = 0; i < 2; ++i) {
        *(uint4*)(&As[0][aOff + i * 8]) = ra[i];
        *(uint4*)(&Bs[0][bOff + i * 8]) = rb[i];
    }
    __syncthreads();

    int buf = 0;
    const int T = DM_ / 32;
    for (int t = 0; t < T; ++t) {
        if (t + 1 < T) {
            const __half* a2 = aSrc + (t + 1) * 32;
            const __half* b2 = bSrc + (size_t)(t + 1) * 32 * N;
#pragma unroll
            for (int i = 0; i < 2; ++i) {
                ra[i] = *(const uint4*)(a2 + i * 8);
                rb[i] = *(const uint4*)(b2 + i * 8);
            }
        }

        const uint32_t sA = buf ? sA1 : sA0;
        const uint32_t sB = buf ? sB1 : sB0;
#pragma unroll
        for (int kk = 0; kk < 2; ++kk) {
            uint32_t af[4][4], bf[2][4];
#pragma unroll
            for (int mf = 0; mf < 4; ++mf) {
                uint32_t addr = sA + (uint32_t)((aFragRow + mf * 16) * APITCH +
                                                kk * 16 + aFragCol) * 2;
                LDMX4(af[mf], addr);
            }
#pragma unroll
            for (int np = 0; np < 2; ++np) {
                uint32_t addr = sB + (uint32_t)((kk * 16 + bFragRow) * BPITCH +
                                                bFragCol + np * 16) * 2;
                LDMX4T(bf[np], addr);
            }
#pragma unroll
            for (int mf = 0; mf < 4; ++mf)
#pragma unroll
                for (int np = 0; np < 2; ++np) {
                    MMA_F16(acc[mf][np * 2],     af[mf], (&bf[np][0]));
                    MMA_F16(acc[mf][np * 2 + 1], af[mf], (&bf[np][2]));
                }
        }

        if (t + 1 < T) {
            const int nb = buf ^ 1;
#pragma unroll
            for (int i = 0; i < 2; ++i) {
                *(uint4*)(&As[nb][aOff + i * 8]) = ra[i];
                *(uint4*)(&Bs[nb][bOff + i * 8]) = rb[i];
            }
        }
        __syncthreads();
        buf ^= 1;
    }

#pragma unroll
    for (int mf = 0; mf < 4; ++mf) {
        const int row0 = m0 + wm + mf * 16 + g;
        const int row1 = row0 + 8;
#pragma unroll
        for (int nf = 0; nf < 4; ++nf) {
            const int col0 = n0 + wn + nf * 8 + q * 2;
            if (mode == 1) {
                float* C = (float*)outp;
                *(float2*)(&C[(size_t)row0 * 1024 + col0]) =
                    make_float2(acc[mf][nf][0], acc[mf][nf][1]);
                *(float2*)(&C[(size_t)row1 * 1024 + col0]) =
                    make_float2(acc[mf][nf][2], acc[mf][nf][3]);
            } else {
                __half* C = (__half*)outp;
                const int h = col0 >> 6, d = col0 & 63;
                {
                    int b = row0 >> 11, s = row0 & (S_ - 1);
                    *(__half2*)(&C[((((size_t)b * nh + h) * S_) + s) * DH_ + d]) =
                        __floats2half2_rn(acc[mf][nf][0], acc[mf][nf][1]);
                }
                {
                    int b = row1 >> 11, s = row1 & (S_ - 1);
                    *(__half2*)(&C[((((size_t)b * nh + h) * S_) + s) * DH_ + d]) =
                        __floats2half2_rn(acc[mf][nf][2], acc[mf][nf][3]);
                }
            }
        }
    }
}

// ---------------------------------------------------------------------------
// L2-normalize + RoPE, fp16 in/out, in-place. One warp per row (R7 version —
// coalesced; the R8 thread-per-row variant broke coalescing and regressed).
// ---------------------------------------------------------------------------
#define NQROWS (B_ * H_ * S_)     // 65536
#define NKROWS (B_ * KVH_ * S_)   // 16384

__global__ void norm_rope16_kernel(__half* __restrict__ qh, __half* __restrict__ kh,
                                   const float* __restrict__ cosb, const float* __restrict__ sinb)
{
    int gwarp = (blockIdx.x * blockDim.x + threadIdx.x) >> 5;
    int lane  = threadIdx.x & 31;
    if (gwarp >= NQROWS + NKROWS) return;
    __half* row = (gwarp < NQROWS) ? (qh + (size_t)gwarp * DH_)
                                   : (kh + (size_t)(gwarp - NQROWS) * DH_);
    int s = gwarp & (S_ - 1);

    float e1 = __half2float(row[lane]);
    float e2 = __half2float(row[lane + 32]);
    float ss = e1 * e1 + e2 * e2;
#pragma unroll
    for (int o = 16; o; o >>= 1) ss += __shfl_xor_sync(0xffffffffu, ss, o);
    float inv = 1.0f / (sqrtf(ss) + 1e-8f);
    e1 *= inv; e2 *= inv;

    float c  = cosb[s * 32 + lane];
    float sn = sinb[s * 32 + lane];
    row[lane]      = __float2half_rn(e1 * c  - e2 * sn);
    row[lane + 32] = __float2half_rn(e1 * sn + e2 * c);
}

// ---------------------------------------------------------------------------
// Flash attention, fp16 mma (m16n8k16, fp32 accum). R7 structure:
// block = 64 queries of one (b,h); 128 threads = 4 warps; warp tile m16 x n64.
// NEW vs R7: P stays in registers (accumulator frag layout == A operand frag
// layout) — removes P smem round-trip, 4 ldmatrix, syncwarp, and one
// __syncthreads per chunk. Packing scheme numerically verified in R8.
// ---------------------------------------------------------------------------
#define KPITCH 72

__global__ __launch_bounds__(128) void attn_h16_kernel(const __half* __restrict__ Q,
                                                       const __half* __restrict__ Kb,
                                                       const __half* __restrict__ Vb,
                                                       __half* __restrict__ ctx)
{
    __shared__ __align__(16) __half Ks[64 * KPITCH];
    __shared__ __align__(16) __half Vs[64 * KPITCH];

    const int tid  = threadIdx.x;
    const int lane = tid & 31;
    const int w    = tid >> 5;
    const int g    = lane >> 2;
    const int qq   = lane & 3;
    const int b    = blockIdx.z;
    const int h    = blockIdx.y;
    const int q0   = blockIdx.x * 64;
    const int kvh  = h / NG_;
    const int mrow = w * 16;

    const __half* Qbase = Q  + ((((size_t)b * H_ + h) * S_) + q0) * DH_;
    const __half* Kbase = Kb + (((size_t)b * KVH_ + kvh) * S_) * DH_;
    const __half* Vbase = Vb + (((size_t)b * KVH_ + kvh) * S_) * DH_;

    const uint32_t sK = smem_u32(Ks);
    const uint32_t sV = smem_u32(Vs);

    const int aRow  = (lane & 7) + 8 * ((lane >> 3) & 1);
    const int aCol  = 8 * (lane >> 4);
    const int bRowK = (lane & 7) + 8 * (lane >> 4);
    const int bColK = 8 * ((lane >> 3) & 1);
    const int bRowV = (lane & 7) + 8 * ((lane >> 3) & 1);
    const int bColV = 8 * (lane >> 4);

    // stage Q tile through Ks, pull A-frags into registers
    for (int it = 0; it < 4; ++it) {
        int i = it * 128 + tid;
        int r = i >> 3, c = (i & 7) * 8;
        *(uint4*)(&Ks[r * KPITCH + c]) = *(const uint4*)(&Qbase[(size_t)r * DH_ + c]);
    }
    __syncthreads();
    uint32_t qf[4][4];
#pragma unroll
    for (int kk = 0; kk < 4; ++kk) {
        uint32_t addr = sK + (uint32_t)((mrow + aRow) * KPITCH + kk * 16 + aCol) * 2;
        LDMX4(qf[kk], addr);
    }

    float o[8][4];
#pragma unroll
    for (int nf = 0; nf < 8; ++nf)
#pragma unroll
        for (int j = 0; j < 4; ++j) o[nf][j] = 0.f;
    float m0 = -INFINITY, m1 = -INFINITY, l0 = 0.f, l1 = 0.f;

    const int row0 = q0 + mrow + g;
    const int row1 = row0 + 8;

    int q_lo = q0 - (WINDOW_ - 1); if (q_lo < 0) q_lo = 0;
    const int c_lo = q_lo >> 6;
    const int c_hi = q0 >> 6;
    const int nch  = c_hi - c_lo + 1 + (c_lo > 0 ? 1 : 0);

    for (int it = 0; it < nch; ++it) {
        const int c = (c_lo > 0) ? (it == 0 ? 0 : c_lo + it - 1) : (c_lo + it);

        __syncthreads();   // previous chunk fully consumed
        for (int p = 0; p < 4; ++p) {
            int i = p * 128 + tid;
            int r = i >> 3, cc = (i & 7) * 8;
            *(uint4*)(&Ks[r * KPITCH + cc]) =
                *(const uint4*)(&Kbase[((size_t)(c * 64 + r)) * DH_ + cc]);
            *(uint4*)(&Vs[r * KPITCH + cc]) =
                *(const uint4*)(&Vbase[((size_t)(c * 64 + r)) * DH_ + cc]);
        }
        __syncthreads();

        // ---- S = Q K^T ----
        float s[8][4];
#pragma unroll
        for (int nf = 0; nf < 8; ++nf)
#pragma unroll
            for (int j = 0; j < 4; ++j) s[nf][j] = 0.f;

#pragma unroll
        for (int kk = 0; kk < 4; ++kk) {
#pragma unroll
            for (int np = 0; np < 4; ++np) {
                uint32_t bf[4];
                uint32_t addr = sK + (uint32_t)((np * 16 + bRowK) * KPITCH +
                                                kk * 16 + bColK) * 2;
                LDMX4(bf, addr);
                MMA_F16(s[np * 2],     qf[kk], (&bf[0]));
                MMA_F16(s[np * 2 + 1], qf[kk], (&bf[2]));
            }
        }

        // ---- softcap + mask + row max ----
        float rmax0 = -INFINITY, rmax1 = -INFINITY;
#pragma unroll
        for (int nf = 0; nf < 8; ++nf) {
            const int kc0 = c * 64 + nf * 8 + 2 * qq;
#pragma unroll
            for (int j = 0; j < 4; ++j) {
                const int kc = kc0 + (j & 1);
                const int qr = (j < 2) ? row0 : row1;
                float x = s[nf][j] * ATTN_SCALE_;
                float e = __expf(x * (2.0f / 15.0f));
                x = 15.0f * ((e - 1.0f) / (e + 1.0f));
                bool valid = (kc <= qr) && ((kc + WINDOW_ > qr) || (kc < NGLOBAL_));
                x = valid ? x : -INFINITY;
                s[nf][j] = x;
                if (j < 2) rmax0 = fmaxf(rmax0, x); else rmax1 = fmaxf(rmax1, x);
            }
        }
        rmax0 = fmaxf(rmax0, __shfl_xor_sync(0xffffffffu, rmax0, 1));
        rmax0 = fmaxf(rmax0, __shfl_xor_sync(0xffffffffu, rmax0, 2));
        rmax1 = fmaxf(rmax1, __shfl_xor_sync(0xffffffffu, rmax1, 1));
        rmax1 = fmaxf(rmax1, __shfl_xor_sync(0xffffffffu, rmax1, 2));

        const float mn0 = fmaxf(fmaxf(m0, rmax0), -1e30f);
        const float mn1 = fmaxf(fmaxf(m1, rmax1), -1e30f);
        const float a0 = __expf(m0 - mn0);
        const float a1 = __expf(m1 - mn1);

        float rs0 = 0.f, rs1 = 0.f;
#pragma unroll
        for (int nf = 0; nf < 8; ++nf) {
            float p0 = __expf(s[nf][0] - mn0);
            float p1 = __expf(s[nf][1] - mn0);
            float p2 = __expf(s[nf][2] - mn1);
            float p3 = __expf(s[nf][3] - mn1);
            rs0 += p0 + p1; rs1 += p2 + p3;
            s[nf][0] = p0; s[nf][1] = p1; s[nf][2] = p2; s[nf][3] = p3;
        }
        rs0 += __shfl_xor_sync(0xffffffffu, rs0, 1);
        rs0 += __shfl_xor_sync(0xffffffffu, rs0, 2);
        rs1 += __shfl_xor_sync(0xffffffffu, rs1, 1);
        rs1 += __shfl_xor_sync(0xffffffffu, rs1, 2);
        l0 = l0 * a0 + rs0;
        l1 = l1 * a1 + rs1;
#pragma unroll
        for (int nf = 0; nf < 8; ++nf) {
            o[nf][0] *= a0; o[nf][1] *= a0;
            o[nf][2] *= a1; o[nf][3] *= a1;
        }
        m0 = mn0; m1 = mn1;

        // ---- O += P V, P packed straight from accumulator registers ----
#pragma unroll
        for (int kk = 0; kk < 4; ++kk) {
            uint32_t af[4];
            af[0] = pack_h2(s[2 * kk][0],     s[2 * kk][1]);
            af[1] = pack_h2(s[2 * kk][2],     s[2 * kk][3]);
            af[2] = pack_h2(s[2 * kk + 1][0], s[2 * kk + 1][1]);
            af[3] = pack_h2(s[2 * kk + 1][2], s[2 * kk + 1][3]);
#pragma unroll
            for (int np = 0; np < 4; ++np) {
                uint32_t bv[4];
                uint32_t addr = sV + (uint32_t)((kk * 16 + bRowV) * KPITCH +
                                                np * 16 + bColV) * 2;
                LDMX4T(bv, addr);
                MMA_F16(o[np * 2],     af, (&bv[0]));
                MMA_F16(o[np * 2 + 1], af, (&bv[2]));
            }
        }
    }

    // ---- epilogue: normalize, write fp16 ctx[b][s][h][d] ----
    const float inv0 = 1.0f / l0;
    const float inv1 = 1.0f / l1;
    __half* c0p = ctx + ((((size_t)b * S_ + row0) * H_) + h) * DH_;
    __half* c1p = ctx + ((((size_t)b * S_ + row1) * H_) + h) * DH_;
#pragma unroll
    for (int nf = 0; nf < 8; ++nf) {
        const int d = nf * 8 + 2 * qq;
        *(__half2*)(&c0p[d]) = __floats2half2_rn(o[nf][0] * inv0, o[nf][1] * inv0);
        *(__half2*)(&c1p[d]) = __floats2half2_rn(o[nf][2] * inv1, o[nf][3] * inv1);
    }
}

// ---------------------------------------------------------------------------
// Launch
// ---------------------------------------------------------------------------
extern "C" void kernel_launch(void* const* d_in, const int* in_sizes, int n_in,
                              void* d_out, int out_size)
{
    const float* x    = (const float*)d_in[0];
    const float* cosb = (const float*)d_in[1];
    const float* sinb = (const float*)d_in[2];
    // d_in[3] = mask (pure causal) — computed analytically, unused
    const float* Wq   = (const float*)d_in[4];
    const float* Wk   = (const float*)d_in[5];
    const float* Wv   = (const float*)d_in[6];
    const float* Wo   = (const float*)d_in[7];
    float* out        = (float*)d_out;

    __half *x16, *wq16, *wk16, *wv16, *wo16, *q16, *k16, *v16, *ctx16;
    cudaGetSymbolAddress((void**)&x16,   g_x16);
    cudaGetSymbolAddress((void**)&wq16,  g_wq16);
    cudaGetSymbolAddress((void**)&wk16,  g_wk16);
    cudaGetSymbolAddress((void**)&wv16,  g_wv16);
    cudaGetSymbolAddress((void**)&wo16,  g_wo16);
    cudaGetSymbolAddress((void**)&q16,   g_q16);
    cudaGetSymbolAddress((void**)&k16,   g_k16);
    cudaGetSymbolAddress((void**)&v16,   g_v16);
    cudaGetSymbolAddress((void**)&ctx16, g_ctx16);

    // fp16 conversions
    cvt_half_kernel<<<2048, 256>>>(x, x16, (M_TOT * DM_) / 4);
    cvt_weights_kernel<<<1280, 256>>>(Wq, Wk, Wv, Wo, wq16, wk16, wv16, wo16);

    // Fused QKV projections (fp16 tensor cores), scatter to [b,h,s,d] fp16
    h16_gemm<<<dim3(12, M_TOT / 128), 256>>>(x16, wq16, wk16, wv16, q16, k16, v16, 0);

    // L2-norm + RoPE (q and k, fp16 in-place, single launch, warp-per-row)
    norm_rope16_kernel<<<(NQROWS + NKROWS) / 8, 256>>>(q16, k16, cosb, sinb);

    // Flash attention (fp16 mma, in-register P)
    attn_h16_kernel<<<dim3(S_ / 64, H_, B_), dim3(128)>>>(q16, k16, v16, ctx16);

    // Output projection (fp16 mma, fp32 row-major into d_out)
    h16_gemm<<<dim3(8, M_TOT / 128), 256>>>(ctx16, wo16, nullptr, nullptr,
                                            out, nullptr, nullptr, 1);
}